// round 7
// baseline (speedup 1.0000x reference)
#include <cuda_runtime.h>

// NeighborList: all i<j pairs, minimum-image PBC, cutoff mask.
// Output (float32): [0,P) pair_i | [P,2P) pair_j | [2P,5P) deltas[P,3] | [5P,6P) dist

#define MAXN 8192
#define TPB  256

__device__ float g_x[MAXN], g_y[MAXN], g_z[MAXN];
__device__ float g_inv[9];
__device__ float g_cellm[9];
__device__ int   g_mode;   // 0 = no PBC, 1 = diagonal cell, 2 = general cell

// Fused prep: thread (0,0) inverts/classifies the cell; all threads transpose xyz -> SoA.
__global__ void prep_kernel(const float* __restrict__ xyz,
                            const float* __restrict__ cell, int n) {
    const int k = blockIdx.x * blockDim.x + threadIdx.x;
    if (k < n) {
        g_x[k] = xyz[3 * k + 0];
        g_y[k] = xyz[3 * k + 1];
        g_z[k] = xyz[3 * k + 2];
    }
    if (blockIdx.x == 0 && threadIdx.x == 0) {
        bool zero = true;
        float c[9];
#pragma unroll
        for (int q = 0; q < 9; q++) {
            c[q] = cell[q];
            if (c[q] != 0.0f) zero = false;
        }
        if (zero) {
            c[0] = c[4] = c[8] = 1.0f;
            c[1] = c[2] = c[3] = c[5] = c[6] = c[7] = 0.0f;
        }
#pragma unroll
        for (int q = 0; q < 9; q++) g_cellm[q] = c[q];

        float a = c[0], b = c[1], cc = c[2];
        float d = c[3], e = c[4], f  = c[5];
        float g = c[6], h = c[7], i  = c[8];
        float A =  (e * i - f * h);
        float B = -(d * i - f * g);
        float C =  (d * h - e * g);
        float det = a * A + b * B + cc * C;
        float invdet = 1.0f / det;
        g_inv[0] = A * invdet;
        g_inv[1] = -(b * i - cc * h) * invdet;
        g_inv[2] =  (b * f - cc * e) * invdet;
        g_inv[3] = B * invdet;
        g_inv[4] =  (a * i - cc * g) * invdet;
        g_inv[5] = -(a * f - cc * d) * invdet;
        g_inv[6] = C * invdet;
        g_inv[7] = -(a * h - b * g) * invdet;
        g_inv[8] =  (a * e - b * d) * invdet;

        const bool diag = (c[1] == 0.0f) && (c[2] == 0.0f) && (c[3] == 0.0f) &&
                          (c[5] == 0.0f) && (c[6] == 0.0f) && (c[7] == 0.0f);
        g_mode = zero ? 0 : (diag ? 1 : 2);
    }
}

__device__ __forceinline__ unsigned tri_off(unsigned i, unsigned T) {
    return (i * (T - i)) >> 1;   // i*(2n-1-i)/2
}

__device__ __forceinline__ float fast_sqrt(float x) {
    float r;
    asm("sqrt.approx.f32 %0, %1;" : "=f"(r) : "f"(x));
    return r;
}

__global__ void __launch_bounds__(TPB)
nl_kernel(float* __restrict__ out, int n, unsigned P) {
    const unsigned t = blockIdx.x * TPB + threadIdx.x;
    const unsigned p = 4u * t;
    if (p >= P) return;

    const unsigned T = 2u * (unsigned)n - 1u;

    // ---- unrank p -> (i, j) ----
    const unsigned D = T * T - 8u * p;
    const float s = sqrtf((float)D);
    int i = (int)(((float)T - s) * 0.5f);
    if (i < 0) i = 0;
    if (i > n - 2) i = n - 2;
    unsigned offi = tri_off((unsigned)i, T);
    while (offi > p) { i--; offi = tri_off((unsigned)i, T); }
    unsigned rowend = tri_off((unsigned)(i + 1), T);
    while (rowend <= p && i < n - 2) {
        i++; offi = rowend; rowend = tri_off((unsigned)(i + 1), T);
    }
    int j = i + 1 + (int)(p - offi);

    // ---- hoist cell data (uniform branches, once per thread) ----
    const int mode = g_mode;
    float d0 = 0.f, d4 = 0.f, d8 = 0.f, e0 = 0.f, e4 = 0.f, e8 = 0.f;  // diag
    float inv[9], cel[9];                                               // general
    if (mode == 1) {
        d0 = g_inv[0]; d4 = g_inv[4]; d8 = g_inv[8];
        e0 = g_cellm[0]; e4 = g_cellm[4]; e8 = g_cellm[8];
    } else if (mode == 2) {
#pragma unroll
        for (int q = 0; q < 9; q++) { inv[q] = g_inv[q]; cel[q] = g_cellm[q]; }
    }

    float xi = g_x[i], yi = g_y[i], zi = g_z[i];

    float oi[4], oj[4], od[4], del[12];
    const unsigned nv = (P - p < 4u) ? (P - p) : 4u;

#pragma unroll
    for (int k = 0; k < 4; k++) {
        if ((unsigned)k >= nv) { oi[k] = oj[k] = od[k] = 0.0f;
                                 del[3*k] = del[3*k+1] = del[3*k+2] = 0.0f; continue; }
        if (p + (unsigned)k == rowend) {        // row crossing (rare)
            i++; j = i + 1;
            rowend = tri_off((unsigned)(i + 1), T);
            xi = g_x[i]; yi = g_y[i]; zi = g_z[i];
        }

        float dx = xi - g_x[j];
        float dy = yi - g_y[j];
        float dz = zi - g_z[j];

        if (mode == 1) {
            // diagonal cell: wrap each axis independently (== matmul with zeros)
            dx -= rintf(dx * d0) * e0;   // jnp.round = half-to-even = rintf
            dy -= rintf(dy * d4) * e4;
            dz -= rintf(dz * d8) * e8;
        } else if (mode == 2) {
            const float f0 = dx * inv[0] + dy * inv[3] + dz * inv[6];
            const float f1 = dx * inv[1] + dy * inv[4] + dz * inv[7];
            const float f2 = dx * inv[2] + dy * inv[5] + dz * inv[8];
            const float r0 = rintf(f0);
            const float r1 = rintf(f1);
            const float r2 = rintf(f2);
            dx -= r0 * cel[0] + r1 * cel[3] + r2 * cel[6];
            dy -= r0 * cel[1] + r1 * cel[4] + r2 * cel[7];
            dz -= r0 * cel[2] + r1 * cel[5] + r2 * cel[8];
        }

        const float dist = fast_sqrt(dx * dx + dy * dy + dz * dz);
        const bool m = (dist <= 5.0f);

        oi[k] = m ? (float)i : -1.0f;
        oj[k] = m ? (float)j : -1.0f;
        od[k] = m ? dist : 0.0f;
        del[3*k + 0] = m ? dx : 0.0f;
        del[3*k + 1] = m ? dy : 0.0f;
        del[3*k + 2] = m ? dz : 0.0f;
        j++;
    }

    if (nv == 4u) {
        // all vector stores are 16B-aligned: P % 4 == 0, p % 4 == 0
        *reinterpret_cast<float4*>(out + p) =
            make_float4(oi[0], oi[1], oi[2], oi[3]);
        *reinterpret_cast<float4*>(out + (size_t)P + p) =
            make_float4(oj[0], oj[1], oj[2], oj[3]);
        *reinterpret_cast<float4*>(out + 5 * (size_t)P + p) =
            make_float4(od[0], od[1], od[2], od[3]);
        float* db = out + 2 * (size_t)P + 3 * (size_t)p;   // byte off 8P+48t, 16B-aligned
        *reinterpret_cast<float4*>(db + 0) = make_float4(del[0], del[1], del[2],  del[3]);
        *reinterpret_cast<float4*>(db + 4) = make_float4(del[4], del[5], del[6],  del[7]);
        *reinterpret_cast<float4*>(db + 8) = make_float4(del[8], del[9], del[10], del[11]);
    } else {
        for (unsigned k = 0; k < nv; k++) {
            out[p + k]                 = oi[k];
            out[(size_t)P + p + k]     = oj[k];
            out[5 * (size_t)P + p + k] = od[k];
            out[2 * (size_t)P + 3 * ((size_t)p + k) + 0] = del[3*k + 0];
            out[2 * (size_t)P + 3 * ((size_t)p + k) + 1] = del[3*k + 1];
            out[2 * (size_t)P + 3 * ((size_t)p + k) + 2] = del[3*k + 2];
        }
    }
}

extern "C" void kernel_launch(void* const* d_in, const int* in_sizes, int n_in,
                              void* d_out, int out_size) {
    const float* xyz  = (const float*)d_in[0];
    const float* cell = (const float*)d_in[1];
    if (n_in >= 2 && in_sizes[0] == 9 && in_sizes[1] != 9) {
        const float* t = xyz; xyz = cell; cell = t;
    }
    const int n = (in_sizes[0] == 9 && n_in >= 2) ? in_sizes[1] / 3 : in_sizes[0] / 3;
    const unsigned P = (unsigned)((size_t)n * (size_t)(n - 1) / 2);

    prep_kernel<<<(n + TPB - 1) / TPB, TPB>>>(xyz, cell, n);

    const unsigned nthreads = (P + 3) / 4;
    const unsigned blocks = (nthreads + TPB - 1) / TPB;
    nl_kernel<<<blocks, TPB>>>((float*)d_out, n, P);
}

// round 8
// speedup vs baseline: 1.1558x; 1.1558x over previous
#include <cuda_runtime.h>

// NeighborList: all i<j pairs, minimum-image PBC, cutoff mask.
// Output (float32): [0,P) pair_i | [P,2P) pair_j | [2P,5P) deltas[P,3] | [5P,6P) dist

#define MAXN 8192
#define TPB  256

__device__ float g_x[MAXN], g_y[MAXN], g_z[MAXN];
__device__ float g_inv[9];
__device__ float g_cellm[9];
__device__ float g_diag[6];   // {inv00,inv11,inv22, cell00,cell11,cell22}; zeros if no PBC
__device__ int   g_general;   // 1 = non-diagonal cell (rare path)

// Fused prep: thread (0,0) inverts/classifies the cell; all threads transpose xyz -> SoA.
__global__ void prep_kernel(const float* __restrict__ xyz,
                            const float* __restrict__ cell, int n) {
    const int k = blockIdx.x * blockDim.x + threadIdx.x;
    if (k < n) {
        g_x[k] = xyz[3 * k + 0];
        g_y[k] = xyz[3 * k + 1];
        g_z[k] = xyz[3 * k + 2];
    }
    if (blockIdx.x == 0 && threadIdx.x == 0) {
        bool zero = true;
        float c[9];
#pragma unroll
        for (int q = 0; q < 9; q++) {
            c[q] = cell[q];
            if (c[q] != 0.0f) zero = false;
        }
        if (zero) {
            c[0] = c[4] = c[8] = 1.0f;
            c[1] = c[2] = c[3] = c[5] = c[6] = c[7] = 0.0f;
        }
#pragma unroll
        for (int q = 0; q < 9; q++) g_cellm[q] = c[q];

        float a = c[0], b = c[1], cc = c[2];
        float d = c[3], e = c[4], f  = c[5];
        float g = c[6], h = c[7], i  = c[8];
        float A =  (e * i - f * h);
        float B = -(d * i - f * g);
        float C =  (d * h - e * g);
        float det = a * A + b * B + cc * C;
        float invdet = 1.0f / det;
        g_inv[0] = A * invdet;
        g_inv[1] = -(b * i - cc * h) * invdet;
        g_inv[2] =  (b * f - cc * e) * invdet;
        g_inv[3] = B * invdet;
        g_inv[4] =  (a * i - cc * g) * invdet;
        g_inv[5] = -(a * f - cc * d) * invdet;
        g_inv[6] = C * invdet;
        g_inv[7] = -(a * h - b * g) * invdet;
        g_inv[8] =  (a * e - b * d) * invdet;

        const bool diag = (c[1] == 0.0f) && (c[2] == 0.0f) && (c[3] == 0.0f) &&
                          (c[5] == 0.0f) && (c[6] == 0.0f) && (c[7] == 0.0f);
        // Diag fast-path scalars. Zeros when no PBC -> wrap becomes exact no-op.
        if (zero) {
            g_diag[0] = g_diag[1] = g_diag[2] = 0.0f;
            g_diag[3] = g_diag[4] = g_diag[5] = 0.0f;
        } else {
            g_diag[0] = g_inv[0]; g_diag[1] = g_inv[4]; g_diag[2] = g_inv[8];
            g_diag[3] = c[0];     g_diag[4] = c[4];     g_diag[5] = c[8];
        }
        g_general = (!zero && !diag) ? 1 : 0;
    }
}

__device__ __forceinline__ unsigned tri_off(unsigned i, unsigned T) {
    return (i * (T - i)) >> 1;   // i*(2n-1-i)/2
}

__device__ __forceinline__ float fast_sqrt(float x) {
    float r;
    asm("sqrt.approx.f32 %0, %1;" : "=f"(r) : "f"(x));
    return r;
}

__global__ void __launch_bounds__(TPB)
nl_kernel(float* __restrict__ out, int n, unsigned P) {
    const unsigned t = blockIdx.x * TPB + threadIdx.x;
    const unsigned p = 4u * t;
    if (p >= P) return;

    const unsigned T = 2u * (unsigned)n - 1u;

    // ---- unrank p -> (i, j) ----
    const unsigned D = T * T - 8u * p;
    const float s = sqrtf((float)D);
    int i = (int)(((float)T - s) * 0.5f);
    if (i < 0) i = 0;
    if (i > n - 2) i = n - 2;
    unsigned offi = tri_off((unsigned)i, T);
    while (offi > p) { i--; offi = tri_off((unsigned)i, T); }
    unsigned rowend = tri_off((unsigned)(i + 1), T);
    while (rowend <= p && i < n - 2) {
        i++; offi = rowend; rowend = tri_off((unsigned)(i + 1), T);
    }
    int j = i + 1 + (int)(p - offi);

    // ---- hoisted state: 6 diag scalars only (zeros => exact no-op wrap) ----
    const int general = g_general;
    const float d0 = g_diag[0], d4 = g_diag[1], d8 = g_diag[2];
    const float e0 = g_diag[3], e4 = g_diag[4], e8 = g_diag[5];

    float xi = g_x[i], yi = g_y[i], zi = g_z[i];

    float oi[4], oj[4], od[4], del[12];
    const unsigned nv = (P - p < 4u) ? (P - p) : 4u;

#pragma unroll
    for (int k = 0; k < 4; k++) {
        if ((unsigned)k >= nv) { oi[k] = oj[k] = od[k] = 0.0f;
                                 del[3*k] = del[3*k+1] = del[3*k+2] = 0.0f; continue; }
        if (p + (unsigned)k == rowend) {        // row crossing (rare)
            i++; j = i + 1;
            rowend = tri_off((unsigned)(i + 1), T);
            xi = g_x[i]; yi = g_y[i]; zi = g_z[i];
        }

        float dx = xi - g_x[j];
        float dy = yi - g_y[j];
        float dz = zi - g_z[j];

        if (!general) {
            // diagonal (or no) PBC: per-axis wrap; zeros make this an exact no-op
            dx -= rintf(dx * d0) * e0;   // jnp.round = half-to-even = rintf
            dy -= rintf(dy * d4) * e4;
            dz -= rintf(dz * d8) * e8;
        } else {
            // rare general-cell path: volatile loads, cannot be hoisted -> no reg cost
            volatile const float* vi9 = g_inv;
            volatile const float* vc9 = g_cellm;
            const float f0 = dx * vi9[0] + dy * vi9[3] + dz * vi9[6];
            const float f1 = dx * vi9[1] + dy * vi9[4] + dz * vi9[7];
            const float f2 = dx * vi9[2] + dy * vi9[5] + dz * vi9[8];
            const float r0 = rintf(f0);
            const float r1 = rintf(f1);
            const float r2 = rintf(f2);
            dx -= r0 * vc9[0] + r1 * vc9[3] + r2 * vc9[6];
            dy -= r0 * vc9[1] + r1 * vc9[4] + r2 * vc9[7];
            dz -= r0 * vc9[2] + r1 * vc9[5] + r2 * vc9[8];
        }

        const float dist = fast_sqrt(dx * dx + dy * dy + dz * dz);
        const bool m = (dist <= 5.0f);

        oi[k] = m ? (float)i : -1.0f;
        oj[k] = m ? (float)j : -1.0f;
        od[k] = m ? dist : 0.0f;
        del[3*k + 0] = m ? dx : 0.0f;
        del[3*k + 1] = m ? dy : 0.0f;
        del[3*k + 2] = m ? dz : 0.0f;
        j++;
    }

    if (nv == 4u) {
        // all vector stores are 16B-aligned: P % 4 == 0, p % 4 == 0
        *reinterpret_cast<float4*>(out + p) =
            make_float4(oi[0], oi[1], oi[2], oi[3]);
        *reinterpret_cast<float4*>(out + (size_t)P + p) =
            make_float4(oj[0], oj[1], oj[2], oj[3]);
        *reinterpret_cast<float4*>(out + 5 * (size_t)P + p) =
            make_float4(od[0], od[1], od[2], od[3]);
        float* db = out + 2 * (size_t)P + 3 * (size_t)p;   // byte off 8P+48t, 16B-aligned
        *reinterpret_cast<float4*>(db + 0) = make_float4(del[0], del[1], del[2],  del[3]);
        *reinterpret_cast<float4*>(db + 4) = make_float4(del[4], del[5], del[6],  del[7]);
        *reinterpret_cast<float4*>(db + 8) = make_float4(del[8], del[9], del[10], del[11]);
    } else {
        for (unsigned k = 0; k < nv; k++) {
            out[p + k]                 = oi[k];
            out[(size_t)P + p + k]     = oj[k];
            out[5 * (size_t)P + p + k] = od[k];
            out[2 * (size_t)P + 3 * ((size_t)p + k) + 0] = del[3*k + 0];
            out[2 * (size_t)P + 3 * ((size_t)p + k) + 1] = del[3*k + 1];
            out[2 * (size_t)P + 3 * ((size_t)p + k) + 2] = del[3*k + 2];
        }
    }
}

extern "C" void kernel_launch(void* const* d_in, const int* in_sizes, int n_in,
                              void* d_out, int out_size) {
    const float* xyz  = (const float*)d_in[0];
    const float* cell = (const float*)d_in[1];
    if (n_in >= 2 && in_sizes[0] == 9 && in_sizes[1] != 9) {
        const float* t = xyz; xyz = cell; cell = t;
    }
    const int n = (in_sizes[0] == 9 && n_in >= 2) ? in_sizes[1] / 3 : in_sizes[0] / 3;
    const unsigned P = (unsigned)((size_t)n * (size_t)(n - 1) / 2);

    prep_kernel<<<(n + TPB - 1) / TPB, TPB>>>(xyz, cell, n);

    const unsigned nthreads = (P + 3) / 4;
    const unsigned blocks = (nthreads + TPB - 1) / TPB;
    nl_kernel<<<blocks, TPB>>>((float*)d_out, n, P);
}